// round 2
// baseline (speedup 1.0000x reference)
#include <cuda_runtime.h>
#include <math.h>

#define BATCH 8
#define SEQ   4096
#define DIM   64
#define TQ    64
#define TK    64
#define KSTR  68   // Ks row stride (floats): 68 % 32 == 4 -> conflict-free LDS.128 phases

// exp(x) for x <= 0 without MUFU: exp(x) = 2^(x*log2e), degree-5 Taylor on the
// fractional part (|f|<=0.5, rel err ~1e-6), exponent spliced via integer add.
__device__ __forceinline__ float fast_exp_neg(float x) {
    float z = fmaxf(x * 1.44269504089f, -126.0f);
    float r = rintf(z);
    float f = z - r;
    float p = 1.33335581e-3f;
    p = fmaf(p, f, 9.61812910e-3f);
    p = fmaf(p, f, 5.55041087e-2f);
    p = fmaf(p, f, 2.40226507e-1f);
    p = fmaf(p, f, 6.93147181e-1f);
    p = fmaf(p, f, 1.0f);
    return __int_as_float(__float_as_int(p) + (((int)r) << 23));
}

// Fused flash-style self-attention: Y = softmax(X X^T) X, per batch.
// Grid: (SEQ/TQ, BATCH). Block: 256 threads as 16x16 (ty=rows, tx=cols),
// each thread owns a 4x4 micro-tile. Online softmax; P bounced via SMEM.
__global__ __launch_bounds__(256, 2)
void attn_fused_kernel(const float* __restrict__ X, float* __restrict__ Y) {
    extern __shared__ float sm[];
    float* Qs = sm;                        // TQ x DIM   (stride 64)
    float* Ks = Qs + TQ * DIM;             // TK x KSTR  (stride 68)
    float* Ps = Ks + TK * KSTR;            // TQ x DIM   (stride 64)

    const int b   = blockIdx.y;
    const int q0  = blockIdx.x * TQ;
    const int tid = threadIdx.x;
    const int tx  = tid & 15;
    const int ty  = tid >> 4;

    const float* Xb = X + (size_t)b * SEQ * DIM;

    // ---- Load Q tile (coalesced, float4) ----
    #pragma unroll
    for (int t = 0; t < 4; t++) {
        int e   = tid + t * 256;       // float4 index within 64x64 tile
        int row = e >> 4;              // 16 float4 per row
        int c4  = (e & 15) << 2;
        float4 v = *(const float4*)&Xb[(q0 + row) * DIM + c4];
        *(float4*)&Qs[row * DIM + c4] = v;
    }

    float m[4], l[4], o[4][4];
    #pragma unroll
    for (int i = 0; i < 4; i++) {
        m[i] = -INFINITY; l[i] = 0.f;
        #pragma unroll
        for (int j = 0; j < 4; j++) o[i][j] = 0.f;
    }

    for (int kt = 0; kt < SEQ; kt += TK) {
        __syncthreads();   // previous O-GEMM done reading Ks/Ps

        // ---- Load K tile (= V tile) ----
        #pragma unroll
        for (int t = 0; t < 4; t++) {
            int e   = tid + t * 256;
            int row = e >> 4;
            int c4  = (e & 15) << 2;
            float4 v = *(const float4*)&Xb[(kt + row) * DIM + c4];
            *(float4*)&Ks[row * KSTR + c4] = v;
        }
        __syncthreads();

        // ---- S = Q K^T : rows r = ty*4+i, cols c = tx + 16*j ----
        float s[4][4];
        #pragma unroll
        for (int i = 0; i < 4; i++)
            #pragma unroll
            for (int j = 0; j < 4; j++) s[i][j] = 0.f;

        #pragma unroll
        for (int d4 = 0; d4 < DIM; d4 += 4) {
            float4 qv[4], kv[4];
            #pragma unroll
            for (int i = 0; i < 4; i++)
                qv[i] = *(const float4*)&Qs[(ty * 4 + i) * DIM + d4];   // broadcast
            #pragma unroll
            for (int j = 0; j < 4; j++)
                kv[j] = *(const float4*)&Ks[(tx + 16 * j) * KSTR + d4]; // conflict-free
            #pragma unroll
            for (int i = 0; i < 4; i++)
                #pragma unroll
                for (int j = 0; j < 4; j++)
                    s[i][j] += qv[i].x * kv[j].x + qv[i].y * kv[j].y +
                               qv[i].z * kv[j].z + qv[i].w * kv[j].w;
        }

        // ---- Online softmax per row (reduce across tx, width-16 shuffles) ----
        #pragma unroll
        for (int i = 0; i < 4; i++) {
            float mt = fmaxf(fmaxf(s[i][0], s[i][1]), fmaxf(s[i][2], s[i][3]));
            #pragma unroll
            for (int off = 8; off; off >>= 1)
                mt = fmaxf(mt, __shfl_xor_sync(0xffffffffu, mt, off, 16));
            float mn    = fmaxf(m[i], mt);
            float scale = fast_exp_neg(m[i] - mn);
            float rs = 0.f;
            #pragma unroll
            for (int j = 0; j < 4; j++) { s[i][j] = fast_exp_neg(s[i][j] - mn); rs += s[i][j]; }
            #pragma unroll
            for (int off = 8; off; off >>= 1)
                rs += __shfl_xor_sync(0xffffffffu, rs, off, 16);
            l[i] = l[i] * scale + rs;
            m[i] = mn;
            #pragma unroll
            for (int j = 0; j < 4; j++) o[i][j] *= scale;
            #pragma unroll
            for (int j = 0; j < 4; j++)
                Ps[(ty * 4 + i) * DIM + tx + 16 * j] = s[i][j];
        }
        __syncthreads();

        // ---- O += P * K : dcols dc = tx*4+j (contiguous float4 K reads) ----
        #pragma unroll
        for (int c4 = 0; c4 < TK; c4 += 4) {
            float4 pv[4];
            #pragma unroll
            for (int i = 0; i < 4; i++)
                pv[i] = *(const float4*)&Ps[(ty * 4 + i) * DIM + c4];   // broadcast
            #pragma unroll
            for (int cc = 0; cc < 4; cc++) {
                float4 kv = *(const float4*)&Ks[(c4 + cc) * KSTR + tx * 4]; // contiguous
                #pragma unroll
                for (int i = 0; i < 4; i++) {
                    float p = (cc == 0) ? pv[i].x : (cc == 1) ? pv[i].y
                            : (cc == 2) ? pv[i].z : pv[i].w;
                    o[i][0] += p * kv.x;
                    o[i][1] += p * kv.y;
                    o[i][2] += p * kv.z;
                    o[i][3] += p * kv.w;
                }
            }
        }
    }

    // ---- Normalize and write out (coalesced float4) ----
    #pragma unroll
    for (int i = 0; i < 4; i++) {
        float inv = 1.f / l[i];
        float4 v = make_float4(o[i][0] * inv, o[i][1] * inv,
                               o[i][2] * inv, o[i][3] * inv);
        *(float4*)&Y[((size_t)b * SEQ + q0 + ty * 4 + i) * DIM + tx * 4] = v;
    }
}

extern "C" void kernel_launch(void* const* d_in, const int* in_sizes, int n_in,
                              void* d_out, int out_size) {
    const float* X = (const float*)d_in[0];
    float* Y = (float*)d_out;

    const int smem_bytes = (TQ * DIM + TK * KSTR + TQ * DIM) * (int)sizeof(float); // 50176
    cudaFuncSetAttribute(attn_fused_kernel,
                         cudaFuncAttributeMaxDynamicSharedMemorySize, smem_bytes);

    dim3 grid(SEQ / TQ, BATCH);
    attn_fused_kernel<<<grid, 256, smem_bytes>>>(X, Y);
}

// round 4
// speedup vs baseline: 3.3030x; 3.3030x over previous
#include <cuda_runtime.h>
#include <cuda_bf16.h>
#include <cstdint>
#include <math.h>

#define BATCH 8
#define SEQ   4096
#define DIM   64
#define TQ    128
#define TK    64

#define SMB   144                 // smem row stride bytes (72 bf16): conflict-free ldmatrix
#define SM_QHI 0                  // 128 x 144
#define SM_QLO (128 * SMB)        // 128 x 144
#define SM_KHI (256 * SMB)        // 64 x 144
#define SM_KLO (320 * SMB)        // 64 x 144
#define SM_QN  (384 * SMB)        // 128 floats
#define SMEM_BYTES (384 * SMB + 512)

static __device__ __forceinline__ uint32_t smem_u32(const void* p) {
    uint32_t a;
    asm("{ .reg .u64 t; cvta.to.shared.u64 t, %1; cvt.u32.u64 %0, t; }" : "=r"(a) : "l"(p));
    return a;
}

static __device__ __forceinline__ void ldsm_x4(uint32_t (&r)[4], uint32_t a) {
    asm volatile("ldmatrix.sync.aligned.m8n8.x4.shared.b16 {%0,%1,%2,%3}, [%4];"
                 : "=r"(r[0]), "=r"(r[1]), "=r"(r[2]), "=r"(r[3]) : "r"(a));
}
static __device__ __forceinline__ void ldsm_x4_t(uint32_t (&r)[4], uint32_t a) {
    asm volatile("ldmatrix.sync.aligned.m8n8.x4.trans.shared.b16 {%0,%1,%2,%3}, [%4];"
                 : "=r"(r[0]), "=r"(r[1]), "=r"(r[2]), "=r"(r[3]) : "r"(a));
}
static __device__ __forceinline__ void mma_bf16(float (&d)[4], const uint32_t (&a)[4],
                                                uint32_t b0, uint32_t b1) {
    asm volatile("mma.sync.aligned.m16n8k16.row.col.f32.bf16.bf16.f32 "
                 "{%0,%1,%2,%3}, {%4,%5,%6,%7}, {%8,%9}, {%0,%1,%2,%3};"
                 : "+f"(d[0]), "+f"(d[1]), "+f"(d[2]), "+f"(d[3])
                 : "r"(a[0]), "r"(a[1]), "r"(a[2]), "r"(a[3]), "r"(b0), "r"(b1));
}

// exp(x) without MUFU: 2^(x*log2e) via rint split + deg-5 poly (rel err ~1e-6).
static __device__ __forceinline__ float fast_exp(float x) {
    float z = fmaxf(x * 1.44269504089f, -126.0f);
    float r = rintf(z);
    float f = z - r;
    float p = 1.33335581e-3f;
    p = fmaf(p, f, 9.61812910e-3f);
    p = fmaf(p, f, 5.55041087e-2f);
    p = fmaf(p, f, 2.40226507e-1f);
    p = fmaf(p, f, 6.93147181e-1f);
    p = fmaf(p, f, 1.0f);
    return __int_as_float(__float_as_int(p) + (((int)r) << 23));
}

static __device__ __forceinline__ uint32_t pack_hi(float a, float b) {
    __nv_bfloat162 h = __float22bfloat162_rn(make_float2(a, b));
    return *reinterpret_cast<uint32_t*>(&h);
}
static __device__ __forceinline__ uint32_t pack_lo(float a, float b, uint32_t hbits) {
    __nv_bfloat162 h = *reinterpret_cast<__nv_bfloat162*>(&hbits);
    float2 hf = __bfloat1622float2(h);
    __nv_bfloat162 l = __float22bfloat162_rn(make_float2(a - hf.x, b - hf.y));
    return *reinterpret_cast<uint32_t*>(&l);
}

__global__ __launch_bounds__(256, 2)
void attn_hmma_kernel(const float* __restrict__ X, float* __restrict__ Y) {
    extern __shared__ char smc[];
    const uint32_t smb = smem_u32(smc);
    float* qn = (float*)(smc + SM_QN);

    const int tid  = threadIdx.x;
    const int wid  = tid >> 5;
    const int lane = tid & 31;
    const int q2   = lane >> 3;        // ldmatrix lane quadrant (0..3)
    const int rr   = lane & 7;         // row within quadrant
    const int g    = lane >> 2;        // mma row group (0..7)
    const int sg   = lane & 3;         // mma col group

    const int b  = blockIdx.y;
    const int q0 = blockIdx.x * TQ;
    const float* Xb = X + (size_t)b * SEQ * DIM;

    // ---- Stage Q tile (128x64 fp32 -> bf16 hi/lo in smem) ----
    #pragma unroll
    for (int i = 0; i < 8; i++) {
        int e = tid + (i << 8);
        int r = e >> 4, c4 = e & 15;
        float4 v = *(const float4*)(Xb + (size_t)(q0 + r) * DIM + c4 * 4);
        uint32_t h0 = pack_hi(v.x, v.y), h1 = pack_hi(v.z, v.w);
        uint32_t l0 = pack_lo(v.x, v.y, h0), l1 = pack_lo(v.z, v.w, h1);
        *(uint2*)(smc + SM_QHI + r * SMB + c4 * 8) = make_uint2(h0, h1);
        *(uint2*)(smc + SM_QLO + r * SMB + c4 * 8) = make_uint2(l0, l1);
    }
    // ---- Row norms (softmax shift m = ||q||^2) ----
    if (tid < TQ) {
        const float4* qp = (const float4*)(Xb + (size_t)(q0 + tid) * DIM);
        float s = 0.f;
        #pragma unroll
        for (int i = 0; i < 16; i++) {
            float4 v = qp[i];
            s += v.x * v.x + v.y * v.y + v.z * v.z + v.w * v.w;
        }
        qn[tid] = s;
    }
    __syncthreads();

    const float m0 = qn[wid * 16 + g];
    const float m1 = qn[wid * 16 + g + 8];

    // ---- Precomputed ldmatrix lane addresses ----
    // A (Q, non-trans): rows base + (q2&1)*8 + rr, 16B-chunk (q2>>1) [+2 per kc]
    const uint32_t qa_hi = smb + SM_QHI + (wid * 16 + (q2 & 1) * 8 + rr) * SMB + (q2 >> 1) * 16;
    const uint32_t qa_lo = qa_hi + (SM_QLO - SM_QHI);
    // B for S-GEMM (K^T, non-trans): rows (q2>>1)*8 + rr [+16 rows per n-pair], chunk (q2&1) [+2 per kc]
    const uint32_t kb_hi = smb + SM_KHI + ((q2 >> 1) * 8 + rr) * SMB + (q2 & 1) * 16;
    const uint32_t kb_lo = kb_hi + (SM_KLO - SM_KHI);
    // B for O-GEMM (V, trans): rows (q2&1)*8 + rr [+16 per n-chunk], chunk (q2>>1) [+2 per d-pair]
    const uint32_t vb_hi = smb + SM_KHI + ((q2 & 1) * 8 + rr) * SMB + (q2 >> 1) * 16;
    const uint32_t vb_lo = vb_hi + (SM_KLO - SM_KHI);

    float O[8][4];
    #pragma unroll
    for (int i = 0; i < 8; i++)
        #pragma unroll
        for (int j = 0; j < 4; j++) O[i][j] = 0.f;
    float l0 = 0.f, l1 = 0.f;

    for (int kt = 0; kt < SEQ; kt += TK) {
        __syncthreads();   // all warps done reading previous K tile

        // ---- Stage K tile (=V tile): 64x64 fp32 -> bf16 hi/lo ----
        #pragma unroll
        for (int i = 0; i < 4; i++) {
            int e = tid + (i << 8);
            int r = e >> 4, c4 = e & 15;
            float4 v = *(const float4*)(Xb + (size_t)(kt + r) * DIM + c4 * 4);
            uint32_t h0 = pack_hi(v.x, v.y), h1 = pack_hi(v.z, v.w);
            uint32_t w0 = pack_lo(v.x, v.y, h0), w1 = pack_lo(v.z, v.w, h1);
            *(uint2*)(smc + SM_KHI + r * SMB + c4 * 8) = make_uint2(h0, h1);
            *(uint2*)(smc + SM_KLO + r * SMB + c4 * 8) = make_uint2(w0, w1);
        }
        __syncthreads();

        // ---- S = Q K^T (3-chain bf16 split), S fragments: 8 n-blocks x 4 ----
        float S[8][4];
        #pragma unroll
        for (int i = 0; i < 8; i++)
            #pragma unroll
            for (int j = 0; j < 4; j++) S[i][j] = 0.f;

        #pragma unroll
        for (int kc = 0; kc < 4; kc++) {
            uint32_t ah[4], al[4];
            ldsm_x4(ah, qa_hi + kc * 32);
            ldsm_x4(al, qa_lo + kc * 32);
            #pragma unroll
            for (int j = 0; j < 4; j++) {           // n-block pairs
                uint32_t bh[4], bl[4];
                ldsm_x4(bh, kb_hi + j * (16 * SMB) + kc * 32);
                ldsm_x4(bl, kb_lo + j * (16 * SMB) + kc * 32);
                mma_bf16(S[2*j],   ah, bh[0], bh[1]);
                mma_bf16(S[2*j+1], ah, bh[2], bh[3]);
                mma_bf16(S[2*j],   ah, bl[0], bl[1]);
                mma_bf16(S[2*j+1], ah, bl[2], bl[3]);
                mma_bf16(S[2*j],   al, bh[0], bh[1]);
                mma_bf16(S[2*j+1], al, bh[2], bh[3]);
            }
        }

        // ---- P = exp(S - m), pack to bf16 hi/lo A-fragments ----
        uint32_t PH[8][2], PL[8][2];
        #pragma unroll
        for (int jb = 0; jb < 8; jb++) {
            float e0 = fast_exp(S[jb][0] - m0);
            float e1 = fast_exp(S[jb][1] - m0);
            float e2 = fast_exp(S[jb][2] - m1);
            float e3 = fast_exp(S[jb][3] - m1);
            l0 += e0 + e1;
            l1 += e2 + e3;
            PH[jb][0] = pack_hi(e0, e1); PL[jb][0] = pack_lo(e0, e1, PH[jb][0]);
            PH[jb][1] = pack_hi(e2, e3); PL[jb][1] = pack_lo(e2, e3, PH[jb][1]);
        }

        // ---- O += P V (V = K tile via ldmatrix.trans, 3-chain split) ----
        #pragma unroll
        for (int nc = 0; nc < 4; nc++) {
            uint32_t pah[4] = {PH[2*nc][0], PH[2*nc][1], PH[2*nc+1][0], PH[2*nc+1][1]};
            uint32_t pal[4] = {PL[2*nc][0], PL[2*nc][1], PL[2*nc+1][0], PL[2*nc+1][1]};
            #pragma unroll
            for (int cp = 0; cp < 4; cp++) {        // d-block pairs
                uint32_t bh[4], bl[4];
                ldsm_x4_t(bh, vb_hi + nc * (16 * SMB) + cp * 32);
                ldsm_x4_t(bl, vb_lo + nc * (16 * SMB) + cp * 32);
                mma_bf16(O[2*cp],   pah, bh[0], bh[1]);
                mma_bf16(O[2*cp+1], pah, bh[2], bh[3]);
                mma_bf16(O[2*cp],   pah, bl[0], bl[1]);
                mma_bf16(O[2*cp+1], pah, bl[2], bl[3]);
                mma_bf16(O[2*cp],   pal, bh[0], bh[1]);
                mma_bf16(O[2*cp+1], pal, bh[2], bh[3]);
            }
        }
    }

    // ---- Epilogue: reduce l over the 4 lanes sharing a row, normalize, store ----
    l0 += __shfl_xor_sync(0xffffffffu, l0, 1);
    l0 += __shfl_xor_sync(0xffffffffu, l0, 2);
    l1 += __shfl_xor_sync(0xffffffffu, l1, 1);
    l1 += __shfl_xor_sync(0xffffffffu, l1, 2);
    const float inv0 = 1.f / l0;
    const float inv1 = 1.f / l1;

    const int row0 = q0 + wid * 16 + g;
    float* y0 = Y + ((size_t)b * SEQ + row0) * DIM + 2 * sg;
    float* y1 = y0 + 8 * DIM;
    #pragma unroll
    for (int jb = 0; jb < 8; jb++) {
        *(float2*)(y0 + jb * 8) = make_float2(O[jb][0] * inv0, O[jb][1] * inv0);
        *(float2*)(y1 + jb * 8) = make_float2(O[jb][2] * inv1, O[jb][3] * inv1);
    }
}

extern "C" void kernel_launch(void* const* d_in, const int* in_sizes, int n_in,
                              void* d_out, int out_size) {
    const float* X = (const float*)d_in[0];
    float* Y = (float*)d_out;

    cudaFuncSetAttribute(attn_hmma_kernel,
                         cudaFuncAttributeMaxDynamicSharedMemorySize, SMEM_BYTES);
    dim3 grid(SEQ / TQ, BATCH);
    attn_hmma_kernel<<<grid, 256, SMEM_BYTES>>>(X, Y);
}